// round 16
// baseline (speedup 1.0000x reference)
#include <cuda_runtime.h>

#define NN 50000
#define NE 1600000
#define HH 64
#define NG 16
#define DOUT 2

#define VPAD 68
#define NODES_B 128

// Scratch (device globals; zero-initialized at load; consumers tail-zero)
__device__ __align__(16) float g_relu_sum[NN * HH];
__device__ float g_deg[NN];
__device__ __align__(16) float g_pooled[NG * HH];   // pooled t (pre-nw2)
__device__ float g_cntf[NG];                        // nodes per graph
__device__ __align__(16) float g_M[64 * 64];        // ew2 @ nw1[1:]
__device__ float g_db[64];                          // eb2 @ nw1[1:]
__device__ int g_done;

// ---------------------------------------------------------------------------
// Prep: M = ew2 @ nw1[1:], db = eb2 @ nw1[1:]. One block, 256 threads.
__global__ void __launch_bounds__(256) prep_kernel(
    const float* __restrict__ ew2, const float* __restrict__ eb2,
    const float* __restrict__ nw1)
{
    __shared__ float s1[64 * 64];       // nw1 rows 1..64
    int tid = threadIdx.x;
    for (int i = tid; i < 4096; i += 256) s1[i] = nw1[64 + i];
    __syncthreads();

    int j = tid & 63, qt = tid >> 6;    // thread: col j, rows qt*16..qt*16+15
#pragma unroll 4
    for (int i = qt * 16; i < qt * 16 + 16; i++) {
        float acc = 0.f;
#pragma unroll 16
        for (int k = 0; k < 64; k++)
            acc = fmaf(__ldg(&ew2[i * 64 + k]), s1[k * 64 + j], acc);
        g_M[i * 64 + j] = acc;
    }
    if (tid < 64) {
        float acc = 0.f;
#pragma unroll 16
        for (int k = 0; k < 64; k++)
            acc = fmaf(__ldg(&eb2[k]), s1[k * 64 + tid], acc);
        g_db[tid] = acc;
    }
}

// ---------------------------------------------------------------------------
// Edge scatter (R13/R15 best config): warp processes 32 edges.
__global__ void __launch_bounds__(256) edge_kernel(
    const float* __restrict__ x,
    const int* __restrict__ ei,
    const float* __restrict__ ea,
    const float* __restrict__ ew1,   // [5,64]
    const float* __restrict__ eb1)   // [64]
{
    __shared__ __align__(16) float4 st4[8][32];
    __shared__ float stx[8][32];
    __shared__ int   stc[8][32];

    int warp = threadIdx.x >> 5, lane = threadIdx.x & 31;
    int e = (blockIdx.x * 8 + warp) * 32 + lane;   // NE % 256 == 0

    int ja = lane, jb = lane + 32;
    float w0a = __ldg(&ew1[0 * 64 + ja]), w1a = __ldg(&ew1[1 * 64 + ja]);
    float w2a = __ldg(&ew1[2 * 64 + ja]), w3a = __ldg(&ew1[3 * 64 + ja]);
    float w4a = __ldg(&ew1[4 * 64 + ja]), ba  = __ldg(&eb1[ja]);
    float w0b = __ldg(&ew1[0 * 64 + jb]), w1b = __ldg(&ew1[1 * 64 + jb]);
    float w2b = __ldg(&ew1[2 * 64 + jb]), w3b = __ldg(&ew1[3 * 64 + jb]);
    float w4b = __ldg(&ew1[4 * 64 + jb]), bb  = __ldg(&eb1[jb]);

    int r = __ldg(&ei[e]);
    int c = __ldg(&ei[NE + e]);
    float xr = __ldg(&x[r]);
    float xc = __ldg(&x[c]);
    float a0 = __ldg(&ea[3 * e + 0]);
    float a1 = __ldg(&ea[3 * e + 1]);
    float a2 = __ldg(&ea[3 * e + 2]);
    atomicAdd(&g_deg[c], 1.0f);

    st4[warp][lane] = make_float4(xr, a0, a1, a2);
    stx[warp][lane] = xc;
    stc[warp][lane] = c;
    __syncwarp();

#pragma unroll 8
    for (int k = 0; k < 32; k++) {
        float4 s  = st4[warp][k];
        float xck = stx[warp][k];
        int   ck  = stc[warp][k];
        float h0 = fmaf(s.x, w0a, fmaf(xck, w1a,
                   fmaf(s.y, w2a, fmaf(s.z, w3a, fmaf(s.w, w4a, ba)))));
        float h1 = fmaf(s.x, w0b, fmaf(xck, w1b,
                   fmaf(s.y, w2b, fmaf(s.z, w3b, fmaf(s.w, w4b, bb)))));
        float* dst = &g_relu_sum[(size_t)ck * HH];
        atomicAdd(dst + ja, fmaxf(h0, 0.f));
        atomicAdd(dst + jb, fmaxf(h1, 0.f));
    }
}

// ---------------------------------------------------------------------------
// dot64 with 4 independent accumulator chains (R15).
__device__ __forceinline__ float dot64(const float* __restrict__ row,
                                       const float* __restrict__ w, float acc) {
    float a0 = acc, a1 = 0.f, a2 = 0.f, a3 = 0.f;
#pragma unroll
    for (int kb = 0; kb < 4; kb++) {
        float4 v0 = *(const float4*)&row[(kb * 4 + 0) * 4];
        float4 v1 = *(const float4*)&row[(kb * 4 + 1) * 4];
        float4 v2 = *(const float4*)&row[(kb * 4 + 2) * 4];
        float4 v3 = *(const float4*)&row[(kb * 4 + 3) * 4];
        const float* w0 = &w[(kb * 4 + 0) * 4];
        const float* w1 = &w[(kb * 4 + 1) * 4];
        const float* w2 = &w[(kb * 4 + 2) * 4];
        const float* w3 = &w[(kb * 4 + 3) * 4];
        a0 = fmaf(v0.x, w0[0], a0); a1 = fmaf(v1.x, w1[0], a1);
        a2 = fmaf(v2.x, w2[0], a2); a3 = fmaf(v3.x, w3[0], a3);
        a0 = fmaf(v0.y, w0[1], a0); a1 = fmaf(v1.y, w1[1], a1);
        a2 = fmaf(v2.y, w2[1], a2); a3 = fmaf(v3.y, w3[1], a3);
        a0 = fmaf(v0.z, w0[2], a0); a1 = fmaf(v1.z, w1[2], a1);
        a2 = fmaf(v2.z, w2[2], a2); a3 = fmaf(v3.z, w3[2], a3);
        a0 = fmaf(v0.w, w0[3], a0); a1 = fmaf(v1.w, w1[3], a1);
        a2 = fmaf(v2.w, w2[3], a2); a3 = fmaf(v3.w, w3[3], a3);
    }
    return (a0 + a1) + (a2 + a3);
}

// ---------------------------------------------------------------------------
// Node kernel: ONE fused GEMV per node:
//   t = relu(nb1 + x*nw1[0] + deg*db + S @ M);  pool t per graph; count nodes.
// Head (last block): pooled_h = cnt*nb2 + pooled_t @ nw2, then 3-layer MLP.
__global__ void __launch_bounds__(256, 3) node_out_kernel(
    const float* __restrict__ x,
    const int* __restrict__ batch,
    const float* __restrict__ nw1, const float* __restrict__ nb1,
    const float* __restrict__ nw2, const float* __restrict__ nb2,
    const float* __restrict__ ow1, const float* __restrict__ ob1,
    const float* __restrict__ ow2, const float* __restrict__ ob2,
    const float* __restrict__ ow3, const float* __restrict__ ob3,
    const float* __restrict__ ow4, const float* __restrict__ ob4,
    float* __restrict__ out)
{
    extern __shared__ __align__(16) float sm[];
    float* svec  = sm;                               // NODES_B*VPAD = 8704
    float* sdg   = sm + NODES_B * VPAD;              // 128
    float* sxn   = sdg + NODES_B;                    // 128
    int*   sgb   = (int*)(sxn + NODES_B);            // 128
    float* spool = sxn + 2 * NODES_B;                // 1024
    float* scnt  = spool + NG * HH;                  // 16

    int tid = threadIdx.x;
    int base = blockIdx.x * NODES_B;
    int nblk = min(NODES_B, NN - base);

    for (int i = tid; i < NG * HH; i += 256) spool[i] = 0.f;
    if (tid < NG) scnt[tid] = 0.f;

    float4* gin = (float4*)g_relu_sum + (size_t)base * 16;
    const float4 z4 = make_float4(0.f, 0.f, 0.f, 0.f);
    for (int i = tid; i < nblk * 16; i += 256) {
        int nn = i >> 4, kv = i & 15;
        *(float4*)&svec[nn * VPAD + kv * 4] = gin[i];
        gin[i] = z4;
    }
    __syncthreads();                                 // scnt zero before atomics

    if (tid < nblk) {
        int n = base + tid;
        sdg[tid] = g_deg[n];
        g_deg[n] = 0.f;
        sxn[tid] = __ldg(&x[n]);
        int g = batch[n];
        sgb[tid] = g;
        atomicAdd(&scnt[g], 1.0f);
    }
    __syncthreads();

    int j = tid & 63;
    int mslot = tid >> 6;

    float w[64];
#pragma unroll
    for (int k = 0; k < 64; k++) w[k] = __ldg(&g_M[k * 64 + j]);
    float dbj = __ldg(&g_db[j]);
    float bj  = __ldg(&nb1[j]);
    float w0j = __ldg(&nw1[j]);                      // nw1 row 0 (x term)

#pragma unroll 2
    for (int i = 0; i < NODES_B / 4; i++) {
        int n = mslot + i * 4;
        if (n < nblk) {
            float pre = fmaf(sxn[n], w0j, fmaf(sdg[n], dbj, bj));
            float t = fmaxf(dot64(&svec[n * VPAD], w, pre), 0.f);
            atomicAdd(&spool[sgb[n] * HH + j], t);
        }
    }
    __syncthreads();
    for (int i = tid; i < NG * HH; i += 256)
        atomicAdd(&g_pooled[i], spool[i]);
    if (tid < NG) atomicAdd(&g_cntf[tid], scnt[tid]);

    // ---- last-block: head MLP ----
    __shared__ int s_last;
    __syncthreads();
    if (tid == 0) {
        __threadfence();
        int done = atomicAdd(&g_done, 1);
        s_last = (done == (int)gridDim.x - 1) ? 1 : 0;
    }
    __syncthreads();
    if (!s_last) return;
    __threadfence();

    float* sa   = spool;                             // pooled_t
    float* sbuf = svec;                              // scratch (8704 floats)
    for (int i = tid; i < NG * HH; i += 256) {
        sa[i] = __ldcg(&g_pooled[i]);
        g_pooled[i] = 0.f;
    }
    if (tid < NG) {
        scnt[tid] = __ldcg(&g_cntf[tid]);
        g_cntf[tid] = 0.f;
    }
    if (tid == 0) g_done = 0;
    __syncthreads();

    // pooled_h = cnt*nb2 + pooled_t @ nw2   -> sbuf
#pragma unroll
    for (int it = 0; it < 4; it++) {
        int item = tid + it * 256;
        int gg = item >> 6, jj = item & 63;
        float v = scnt[gg] * __ldg(&nb2[jj]);
#pragma unroll 16
        for (int k = 0; k < 64; k++) v = fmaf(sa[gg * 64 + k], __ldg(&nw2[k * 64 + jj]), v);
        sbuf[item] = v;
    }
    __syncthreads();
    // L1: sa = relu(sbuf@ow1+ob1)
#pragma unroll
    for (int it = 0; it < 4; it++) {
        int item = tid + it * 256;
        int gg = item >> 6, jj = item & 63;
        float v = __ldg(&ob1[jj]);
#pragma unroll 16
        for (int k = 0; k < 64; k++) v = fmaf(sbuf[gg * 64 + k], __ldg(&ow1[k * 64 + jj]), v);
        sa[item] = fmaxf(v, 0.f);
    }
    __syncthreads();
    // L2: sbuf = relu(sa@ow2+ob2)
#pragma unroll
    for (int it = 0; it < 4; it++) {
        int item = tid + it * 256;
        int gg = item >> 6, jj = item & 63;
        float v = __ldg(&ob2[jj]);
#pragma unroll 16
        for (int k = 0; k < 64; k++) v = fmaf(sa[gg * 64 + k], __ldg(&ow2[k * 64 + jj]), v);
        sbuf[item] = fmaxf(v, 0.f);
    }
    __syncthreads();
    // L3: sa = relu(sbuf@ow3+ob3)
#pragma unroll
    for (int it = 0; it < 4; it++) {
        int item = tid + it * 256;
        int gg = item >> 6, jj = item & 63;
        float v = __ldg(&ob3[jj]);
#pragma unroll 16
        for (int k = 0; k < 64; k++) v = fmaf(sbuf[gg * 64 + k], __ldg(&ow3[k * 64 + jj]), v);
        sa[item] = fmaxf(v, 0.f);
    }
    __syncthreads();
    if (tid < NG * DOUT) {
        int gg = tid / DOUT, jj = tid % DOUT;
        float o = __ldg(&ob4[jj]);
#pragma unroll 16
        for (int k = 0; k < 64; k++)
            o = fmaf(sa[gg * 64 + k], __ldg(&ow4[k * DOUT + jj]), o);
        out[gg * DOUT + jj] = o;
    }
}

// ---------------------------------------------------------------------------
extern "C" void kernel_launch(void* const* d_in, const int* in_sizes, int n_in,
                              void* d_out, int out_size) {
    const float* x     = (const float*)d_in[0];
    const int* ei      = (const int*)d_in[1];
    const float* ea    = (const float*)d_in[2];
    const int* batch   = (const int*)d_in[3];
    const float* ew1 = (const float*)d_in[4];
    const float* eb1 = (const float*)d_in[5];
    const float* ew2 = (const float*)d_in[6];
    const float* eb2 = (const float*)d_in[7];
    const float* nw1 = (const float*)d_in[8];
    const float* nb1 = (const float*)d_in[9];
    const float* nw2 = (const float*)d_in[10];
    const float* nb2 = (const float*)d_in[11];
    const float* ow1 = (const float*)d_in[12];
    const float* ob1 = (const float*)d_in[13];
    const float* ow2 = (const float*)d_in[14];
    const float* ob2 = (const float*)d_in[15];
    const float* ow3 = (const float*)d_in[16];
    const float* ob3 = (const float*)d_in[17];
    const float* ow4 = (const float*)d_in[18];
    const float* ob4 = (const float*)d_in[19];
    float* out = (float*)d_out;

    // svec + sdg + sxn + sgb + spool + scnt
    const int node_smem = (NODES_B * VPAD + 3 * NODES_B + NG * HH + NG) * 4; // 40512 B
    static int smem_set = 0;
    if (!smem_set) {
        cudaFuncSetAttribute(node_out_kernel,
                             cudaFuncAttributeMaxDynamicSharedMemorySize, node_smem);
        smem_set = 1;
    }

    prep_kernel<<<1, 256>>>(ew2, eb2, nw1);                            // 1
    edge_kernel<<<NE / 256, 256>>>(x, ei, ea, ew1, eb1);               // 2
    node_out_kernel<<<(NN + NODES_B - 1) / NODES_B, 256, node_smem>>>( // 3
        x, batch, nw1, nb1, nw2, nb2,
        ow1, ob1, ow2, ob2, ow3, ob3, ow4, ob4, out);
}

// round 17
// speedup vs baseline: 1.1992x; 1.1992x over previous
#include <cuda_runtime.h>

#define NN 50000
#define NE 1600000
#define HH 64
#define NG 16
#define DOUT 2

#define VPAD 68
#define NODES_B 128

#define EB_EDGE_BLOCKS (NE / 256)    // 6250
#define PREP_BLOCKS 16               // 4 rows of M each

// Scratch (device globals; zero-initialized at load; consumers tail-zero)
__device__ __align__(16) float g_relu_sum[NN * HH];
__device__ float g_deg[NN];
__device__ __align__(16) float g_pooled[NG * HH];   // pooled t (pre-nw2)
__device__ float g_cntf[NG];                        // nodes per graph
__device__ __align__(16) float g_M[64 * 64];        // ew2 @ nw1[1:]
__device__ float g_db[64];                          // eb2 @ nw1[1:]
__device__ int g_done;

// ---------------------------------------------------------------------------
// Edge scatter + embedded prep. Blocks [0, 6250): warp processes 32 edges,
// coalesced RED.32 x2 per edge. Blocks [6250, 6266): compute M/db rows
// (hidden inside the edge kernel's duration; no extra launch).
__global__ void __launch_bounds__(256) edge_kernel(
    const float* __restrict__ x,
    const int* __restrict__ ei,
    const float* __restrict__ ea,
    const float* __restrict__ ew1,   // [5,64]
    const float* __restrict__ eb1,   // [64]
    const float* __restrict__ ew2,   // [64,64]
    const float* __restrict__ eb2,   // [64]
    const float* __restrict__ nw1)   // [65,64]
{
    int tid = threadIdx.x;

    if (blockIdx.x >= EB_EDGE_BLOCKS) {
        // ---- prep path: M = ew2 @ nw1[1:], db = eb2 @ nw1[1:] ----
        int bi = blockIdx.x - EB_EDGE_BLOCKS;        // 0..15
        int i = bi * 4 + (tid >> 6);                 // row of M
        int j = tid & 63;                            // col of M
        float acc = 0.f;
#pragma unroll 16
        for (int k = 0; k < 64; k++)
            acc = fmaf(__ldg(&ew2[i * 64 + k]), __ldg(&nw1[(k + 1) * 64 + j]), acc);
        g_M[i * 64 + j] = acc;
        if (bi == 0 && tid < 64) {
            float db = 0.f;
#pragma unroll 16
            for (int k = 0; k < 64; k++)
                db = fmaf(__ldg(&eb2[k]), __ldg(&nw1[(k + 1) * 64 + tid]), db);
            g_db[tid] = db;
        }
        return;
    }

    __shared__ __align__(16) float4 st4[8][32];
    __shared__ float stx[8][32];
    __shared__ int   stc[8][32];

    int warp = tid >> 5, lane = tid & 31;
    int e = (blockIdx.x * 8 + warp) * 32 + lane;     // NE % 256 == 0

    int ja = lane, jb = lane + 32;
    float w0a = __ldg(&ew1[0 * 64 + ja]), w1a = __ldg(&ew1[1 * 64 + ja]);
    float w2a = __ldg(&ew1[2 * 64 + ja]), w3a = __ldg(&ew1[3 * 64 + ja]);
    float w4a = __ldg(&ew1[4 * 64 + ja]), ba  = __ldg(&eb1[ja]);
    float w0b = __ldg(&ew1[0 * 64 + jb]), w1b = __ldg(&ew1[1 * 64 + jb]);
    float w2b = __ldg(&ew1[2 * 64 + jb]), w3b = __ldg(&ew1[3 * 64 + jb]);
    float w4b = __ldg(&ew1[4 * 64 + jb]), bb  = __ldg(&eb1[jb]);

    int r = __ldg(&ei[e]);
    int c = __ldg(&ei[NE + e]);
    float xr = __ldg(&x[r]);
    float xc = __ldg(&x[c]);
    float a0 = __ldg(&ea[3 * e + 0]);
    float a1 = __ldg(&ea[3 * e + 1]);
    float a2 = __ldg(&ea[3 * e + 2]);
    atomicAdd(&g_deg[c], 1.0f);

    st4[warp][lane] = make_float4(xr, a0, a1, a2);
    stx[warp][lane] = xc;
    stc[warp][lane] = c;
    __syncwarp();

#pragma unroll 8
    for (int k = 0; k < 32; k++) {
        float4 s  = st4[warp][k];
        float xck = stx[warp][k];
        int   ck  = stc[warp][k];
        float h0 = fmaf(s.x, w0a, fmaf(xck, w1a,
                   fmaf(s.y, w2a, fmaf(s.z, w3a, fmaf(s.w, w4a, ba)))));
        float h1 = fmaf(s.x, w0b, fmaf(xck, w1b,
                   fmaf(s.y, w2b, fmaf(s.z, w3b, fmaf(s.w, w4b, bb)))));
        float* dst = &g_relu_sum[(size_t)ck * HH];
        atomicAdd(dst + ja, fmaxf(h0, 0.f));
        atomicAdd(dst + jb, fmaxf(h1, 0.f));
    }
}

// ---------------------------------------------------------------------------
// dot64 with 4 independent accumulator chains.
__device__ __forceinline__ float dot64(const float* __restrict__ row,
                                       const float* __restrict__ w, float acc) {
    float a0 = acc, a1 = 0.f, a2 = 0.f, a3 = 0.f;
#pragma unroll
    for (int kb = 0; kb < 4; kb++) {
        float4 v0 = *(const float4*)&row[(kb * 4 + 0) * 4];
        float4 v1 = *(const float4*)&row[(kb * 4 + 1) * 4];
        float4 v2 = *(const float4*)&row[(kb * 4 + 2) * 4];
        float4 v3 = *(const float4*)&row[(kb * 4 + 3) * 4];
        const float* w0 = &w[(kb * 4 + 0) * 4];
        const float* w1 = &w[(kb * 4 + 1) * 4];
        const float* w2 = &w[(kb * 4 + 2) * 4];
        const float* w3 = &w[(kb * 4 + 3) * 4];
        a0 = fmaf(v0.x, w0[0], a0); a1 = fmaf(v1.x, w1[0], a1);
        a2 = fmaf(v2.x, w2[0], a2); a3 = fmaf(v3.x, w3[0], a3);
        a0 = fmaf(v0.y, w0[1], a0); a1 = fmaf(v1.y, w1[1], a1);
        a2 = fmaf(v2.y, w2[1], a2); a3 = fmaf(v3.y, w3[1], a3);
        a0 = fmaf(v0.z, w0[2], a0); a1 = fmaf(v1.z, w1[2], a1);
        a2 = fmaf(v2.z, w2[2], a2); a3 = fmaf(v3.z, w3[2], a3);
        a0 = fmaf(v0.w, w0[3], a0); a1 = fmaf(v1.w, w1[3], a1);
        a2 = fmaf(v2.w, w2[3], a2); a3 = fmaf(v3.w, w3[3], a3);
    }
    return (a0 + a1) + (a2 + a3);
}

// ---------------------------------------------------------------------------
// Node kernel: ONE fused GEMV per node:
//   t = relu(nb1 + x*nw1[0] + deg*db + S @ M);  pool t per graph; count nodes.
// Head (last block): pooled_h = cnt*nb2 + pooled_t @ nw2, then 3-layer MLP.
__global__ void __launch_bounds__(256, 3) node_out_kernel(
    const float* __restrict__ x,
    const int* __restrict__ batch,
    const float* __restrict__ nw1, const float* __restrict__ nb1,
    const float* __restrict__ nw2, const float* __restrict__ nb2,
    const float* __restrict__ ow1, const float* __restrict__ ob1,
    const float* __restrict__ ow2, const float* __restrict__ ob2,
    const float* __restrict__ ow3, const float* __restrict__ ob3,
    const float* __restrict__ ow4, const float* __restrict__ ob4,
    float* __restrict__ out)
{
    extern __shared__ __align__(16) float sm[];
    float* svec  = sm;                               // NODES_B*VPAD = 8704
    float* sdg   = sm + NODES_B * VPAD;              // 128
    float* sxn   = sdg + NODES_B;                    // 128
    int*   sgb   = (int*)(sxn + NODES_B);            // 128
    float* spool = sxn + 2 * NODES_B;                // 1024
    float* scnt  = spool + NG * HH;                  // 16

    int tid = threadIdx.x;
    int base = blockIdx.x * NODES_B;
    int nblk = min(NODES_B, NN - base);

    for (int i = tid; i < NG * HH; i += 256) spool[i] = 0.f;
    if (tid < NG) scnt[tid] = 0.f;

    float4* gin = (float4*)g_relu_sum + (size_t)base * 16;
    const float4 z4 = make_float4(0.f, 0.f, 0.f, 0.f);
    for (int i = tid; i < nblk * 16; i += 256) {
        int nn = i >> 4, kv = i & 15;
        *(float4*)&svec[nn * VPAD + kv * 4] = gin[i];
        gin[i] = z4;
    }
    __syncthreads();                                 // scnt zero before atomics

    if (tid < nblk) {
        int n = base + tid;
        sdg[tid] = g_deg[n];
        g_deg[n] = 0.f;
        sxn[tid] = __ldg(&x[n]);
        int g = batch[n];
        sgb[tid] = g;
        atomicAdd(&scnt[g], 1.0f);
    }
    __syncthreads();

    int j = tid & 63;
    int mslot = tid >> 6;

    float w[64];
#pragma unroll
    for (int k = 0; k < 64; k++) w[k] = __ldg(&g_M[k * 64 + j]);
    float dbj = __ldg(&g_db[j]);
    float bj  = __ldg(&nb1[j]);
    float w0j = __ldg(&nw1[j]);                      // nw1 row 0 (x term)

#pragma unroll 2
    for (int i = 0; i < NODES_B / 4; i++) {
        int n = mslot + i * 4;
        if (n < nblk) {
            float pre = fmaf(sxn[n], w0j, fmaf(sdg[n], dbj, bj));
            float t = fmaxf(dot64(&svec[n * VPAD], w, pre), 0.f);
            atomicAdd(&spool[sgb[n] * HH + j], t);
        }
    }
    __syncthreads();
    for (int i = tid; i < NG * HH; i += 256)
        atomicAdd(&g_pooled[i], spool[i]);
    if (tid < NG) atomicAdd(&g_cntf[tid], scnt[tid]);

    // ---- last-block: head MLP ----
    __shared__ int s_last;
    __syncthreads();
    if (tid == 0) {
        __threadfence();
        int done = atomicAdd(&g_done, 1);
        s_last = (done == (int)gridDim.x - 1) ? 1 : 0;
    }
    __syncthreads();
    if (!s_last) return;
    __threadfence();

    float* sa   = spool;                             // pooled_t
    float* sbuf = svec;                              // scratch (8704 floats)
    for (int i = tid; i < NG * HH; i += 256) {
        sa[i] = __ldcg(&g_pooled[i]);
        g_pooled[i] = 0.f;
    }
    if (tid < NG) {
        scnt[tid] = __ldcg(&g_cntf[tid]);
        g_cntf[tid] = 0.f;
    }
    if (tid == 0) g_done = 0;
    __syncthreads();

    // pooled_h = cnt*nb2 + pooled_t @ nw2   -> sbuf
#pragma unroll
    for (int it = 0; it < 4; it++) {
        int item = tid + it * 256;
        int gg = item >> 6, jj = item & 63;
        float v = scnt[gg] * __ldg(&nb2[jj]);
#pragma unroll 16
        for (int k = 0; k < 64; k++) v = fmaf(sa[gg * 64 + k], __ldg(&nw2[k * 64 + jj]), v);
        sbuf[item] = v;
    }
    __syncthreads();
#pragma unroll
    for (int it = 0; it < 4; it++) {
        int item = tid + it * 256;
        int gg = item >> 6, jj = item & 63;
        float v = __ldg(&ob1[jj]);
#pragma unroll 16
        for (int k = 0; k < 64; k++) v = fmaf(sbuf[gg * 64 + k], __ldg(&ow1[k * 64 + jj]), v);
        sa[item] = fmaxf(v, 0.f);
    }
    __syncthreads();
#pragma unroll
    for (int it = 0; it < 4; it++) {
        int item = tid + it * 256;
        int gg = item >> 6, jj = item & 63;
        float v = __ldg(&ob2[jj]);
#pragma unroll 16
        for (int k = 0; k < 64; k++) v = fmaf(sa[gg * 64 + k], __ldg(&ow2[k * 64 + jj]), v);
        sbuf[item] = fmaxf(v, 0.f);
    }
    __syncthreads();
#pragma unroll
    for (int it = 0; it < 4; it++) {
        int item = tid + it * 256;
        int gg = item >> 6, jj = item & 63;
        float v = __ldg(&ob3[jj]);
#pragma unroll 16
        for (int k = 0; k < 64; k++) v = fmaf(sbuf[gg * 64 + k], __ldg(&ow3[k * 64 + jj]), v);
        sa[item] = fmaxf(v, 0.f);
    }
    __syncthreads();
    if (tid < NG * DOUT) {
        int gg = tid / DOUT, jj = tid % DOUT;
        float o = __ldg(&ob4[jj]);
#pragma unroll 16
        for (int k = 0; k < 64; k++)
            o = fmaf(sa[gg * 64 + k], __ldg(&ow4[k * DOUT + jj]), o);
        out[gg * DOUT + jj] = o;
    }
}

// ---------------------------------------------------------------------------
extern "C" void kernel_launch(void* const* d_in, const int* in_sizes, int n_in,
                              void* d_out, int out_size) {
    const float* x     = (const float*)d_in[0];
    const int* ei      = (const int*)d_in[1];
    const float* ea    = (const float*)d_in[2];
    const int* batch   = (const int*)d_in[3];
    const float* ew1 = (const float*)d_in[4];
    const float* eb1 = (const float*)d_in[5];
    const float* ew2 = (const float*)d_in[6];
    const float* eb2 = (const float*)d_in[7];
    const float* nw1 = (const float*)d_in[8];
    const float* nb1 = (const float*)d_in[9];
    const float* nw2 = (const float*)d_in[10];
    const float* nb2 = (const float*)d_in[11];
    const float* ow1 = (const float*)d_in[12];
    const float* ob1 = (const float*)d_in[13];
    const float* ow2 = (const float*)d_in[14];
    const float* ob2 = (const float*)d_in[15];
    const float* ow3 = (const float*)d_in[16];
    const float* ob3 = (const float*)d_in[17];
    const float* ow4 = (const float*)d_in[18];
    const float* ob4 = (const float*)d_in[19];
    float* out = (float*)d_out;

    const int node_smem = (NODES_B * VPAD + 3 * NODES_B + NG * HH + NG) * 4; // 40512 B
    static int smem_set = 0;
    if (!smem_set) {
        cudaFuncSetAttribute(node_out_kernel,
                             cudaFuncAttributeMaxDynamicSharedMemorySize, node_smem);
        smem_set = 1;
    }

    edge_kernel<<<EB_EDGE_BLOCKS + PREP_BLOCKS, 256>>>(                // 1 (incl. prep)
        x, ei, ea, ew1, eb1, ew2, eb2, nw1);
    node_out_kernel<<<(NN + NODES_B - 1) / NODES_B, 256, node_smem>>>( // 2
        x, batch, nw1, nb1, nw2, nb2,
        ow1, ob1, ow2, ob2, ow3, ob3, ow4, ob4, out);
}